// round 6
// baseline (speedup 1.0000x reference)
#include <cuda_runtime.h>
#include <cstdint>
#include <cstddef>

#define T_DIM 256
#define B_DIM 2048
#define DIN   128
#define NQ    16
#define GN    64
#define M_TOT (T_DIM * B_DIM)

// ZX scratch padded by 4 timesteps so phase-2 prefetch needs no bounds check.
__device__ __align__(256) float g_zx[(size_t)(T_DIM + 4) * B_DIM * GN];

// ===========================================================================
// Phase 1: ZX = X @ Wx^T + (b+theta) via mma.sync m16n8k32 s8 (IMMA),
// exact 16-bit fixed point: X*2^12 = hx*256+lx, W*2^15 = hw*256+lw (signed
// low bytes). z_int = 2^16*hh + 2^8*(hl+lh) + ll, all integer-exact;
// only quantization error remains (~1e-4 rms on z).
//   Block: 256 thr / 8 warps; warp tile m16 x n64; block 128 rows.
//   K=128 staged once (one __syncthreads), smem rows 144B.
//   k-bytes permuted within 32-blocks so (a0,a2)/(a1,a3)/(b0,b1) frag pairs
//   are single LDS.64: p(k) = (k&3) | (((k>>4)&1)<<2) | (((k>>2)&3)<<3).
// ===========================================================================
#define SXQ 4096.0f
#define SWQ 32768.0f
#define INV_SSQ 7.450580596923828e-09f   // 2^-27

#define WH_OFF 256
#define WL_OFF (WH_OFF + 64 * 144)       // 9472
#define XH_OFF (WL_OFF + 64 * 144)       // 18688
#define XL_OFF (XH_OFF + 128 * 144)      // 37120
#define P1_SMEM (XL_OFF + 128 * 144)     // 55552

#define MMA_S8(c, a0, a1, a2, a3, b0, b1) \
    asm volatile("mma.sync.aligned.m16n8k32.row.col.s32.s8.s8.s32 " \
        "{%0,%1,%2,%3}, {%4,%5,%6,%7}, {%8,%9}, {%0,%1,%2,%3};" \
        : "+r"((c)[0]), "+r"((c)[1]), "+r"((c)[2]), "+r"((c)[3]) \
        : "r"(a0), "r"(a1), "r"(a2), "r"(a3), "r"(b0), "r"(b1))

// convert float4 -> (packed hi bytes, packed lo bytes), scale s
__device__ __forceinline__ uint2 q8_split4(float4 v, float s) {
    int i0 = __float2int_rn(v.x * s), i1 = __float2int_rn(v.y * s);
    int i2 = __float2int_rn(v.z * s), i3 = __float2int_rn(v.w * s);
    i0 = max(-32767, min(32767, i0)); i1 = max(-32767, min(32767, i1));
    i2 = max(-32767, min(32767, i2)); i3 = max(-32767, min(32767, i3));
    const int l0 = (i0 << 24) >> 24, l1 = (i1 << 24) >> 24;
    const int l2 = (i2 << 24) >> 24, l3 = (i3 << 24) >> 24;
    const int h0 = (i0 - l0) >> 8, h1 = (i1 - l1) >> 8;
    const int h2 = (i2 - l2) >> 8, h3 = (i3 - l3) >> 8;
    uint2 r;
    r.x = (h0 & 0xff) | ((h1 & 0xff) << 8) | ((h2 & 0xff) << 16) | (h3 << 24);
    r.y = (l0 & 0xff) | ((l1 & 0xff) << 8) | ((l2 & 0xff) << 16) | (l3 << 24);
    return r;
}

// permuted byte offset within a row for the float4 at word q (k = 4q..4q+3)
__device__ __forceinline__ int perm_off(int q) {
    return (q >> 3) * 32 + (q & 3) * 8 + ((q >> 2) & 1) * 4;
}

__global__ __launch_bounds__(256) void qlstm_p1(
    const float* __restrict__ X,
    const float* __restrict__ W,      // [64][144]
    const float* __restrict__ Bb,
    const float* __restrict__ Th)
{
    extern __shared__ char smem[];
    float* bts = (float*)smem;

    const int tid  = threadIdx.x;
    const int lane = tid & 31, w = tid >> 5;
    const int g = lane >> 2, tig = lane & 3;
    const int wr = w * 16;
    const size_t m0 = (size_t)blockIdx.x * 128;

    if (tid < 64) bts[tid] = Bb[tid] + Th[tid];

    // ---- stage X tile (128 x 128) ----
    {
        const int row = tid >> 1, qh = (tid & 1) * 16;   // 2 threads per row
        const float4* Xg = (const float4*)(X + (m0 + row) * DIN) + qh;
#pragma unroll
        for (int i = 0; i < 16; i++) {
            const int q = qh + i;
            const uint2 u = q8_split4(Xg[i], SXQ);
            const int off = row * 144 + perm_off(q);
            *(uint32_t*)(smem + XH_OFF + off) = u.x;
            *(uint32_t*)(smem + XL_OFF + off) = u.y;
        }
    }
    // ---- stage W (64 x 128, gmem row stride 144) ----
    {
        const int row = tid >> 2, qh = (tid & 3) * 8;    // 4 threads per row
#pragma unroll
        for (int i = 0; i < 8; i++) {
            const int q = qh + i;
            const float4 v = *(const float4*)(W + row * 144 + 4 * q);
            const uint2 u = q8_split4(v, SWQ);
            const int off = row * 144 + perm_off(q);
            *(uint32_t*)(smem + WH_OFF + off) = u.x;
            *(uint32_t*)(smem + WL_OFF + off) = u.y;
        }
    }
    __syncthreads();

    int Chh[8][4], Cm[8][4], Cll[8][4];
#pragma unroll
    for (int nt = 0; nt < 8; nt++)
#pragma unroll
        for (int q = 0; q < 4; q++) { Chh[nt][q] = 0; Cm[nt][q] = 0; Cll[nt][q] = 0; }

#pragma unroll
    for (int ks = 0; ks < 4; ks++) {
        const int ko = ks * 32 + tig * 8;
        const uint2 AH0 = *(const uint2*)(smem + XH_OFF + (wr + g) * 144 + ko);
        const uint2 AH1 = *(const uint2*)(smem + XH_OFF + (wr + 8 + g) * 144 + ko);
        const uint2 AL0 = *(const uint2*)(smem + XL_OFF + (wr + g) * 144 + ko);
        const uint2 AL1 = *(const uint2*)(smem + XL_OFF + (wr + 8 + g) * 144 + ko);
#pragma unroll
        for (int nt = 0; nt < 8; nt++) {
            const uint2 BH = *(const uint2*)(smem + WH_OFF + (nt * 8 + g) * 144 + ko);
            const uint2 BL = *(const uint2*)(smem + WL_OFF + (nt * 8 + g) * 144 + ko);
            MMA_S8(Chh[nt], AH0.x, AH1.x, AH0.y, AH1.y, BH.x, BH.y);
            MMA_S8(Cm[nt],  AH0.x, AH1.x, AH0.y, AH1.y, BL.x, BL.y);
            MMA_S8(Cm[nt],  AL0.x, AL1.x, AL0.y, AL1.y, BH.x, BH.y);
            MMA_S8(Cll[nt], AL0.x, AL1.x, AL0.y, AL1.y, BL.x, BL.y);
        }
    }

    // ---- epilogue: z = ((Chh<<8)+Cm)*256 + Cll, scale 2^-27, + (b+theta) ----
    float2 bt2[8];
#pragma unroll
    for (int nt = 0; nt < 8; nt++)
        bt2[nt] = *(const float2*)&bts[nt * 8 + 2 * tig];

    const size_t r0 = m0 + wr + g;
#pragma unroll
    for (int nt = 0; nt < 8; nt++) {
        const int col = nt * 8 + 2 * tig;
        float zz[4];
#pragma unroll
        for (int q = 0; q < 4; q++) {
            const int t = (Chh[nt][q] << 8) + Cm[nt][q];
            zz[q] = fmaf((float)t, 256.0f, (float)Cll[nt][q]) * INV_SSQ;
        }
        *(float2*)&g_zx[r0 * GN + col] =
            make_float2(zz[0] + bt2[nt].x, zz[1] + bt2[nt].y);
        *(float2*)&g_zx[(r0 + 8) * GN + col] =
            make_float2(zz[2] + bt2[nt].x, zz[3] + bt2[nt].y);
    }
}

// ===========================================================================
// Phase 2: recurrence, 16 lanes/element, 2 elements per warp (R4 layout).
//   h broadcast via width-16 shfl (no smem, no barriers); gate dots packed
//   as fma.rn.f32x2 (gates 0,1 | 2,3); radix-4 shfl scan; 4-step prefetch.
// ===========================================================================
#define FMA_X2(d, a, b, c) \
    asm("fma.rn.f32x2 %0, %1, %2, %3;" : "=l"(d) : "l"(a), "l"(b), "l"(c))
#define PACK2(d, x, y) \
    asm("mov.b64 %0, {%1, %2};" : "=l"(d) : "f"(x), "f"(y))
#define UNPACK2(x, y, d) \
    asm("mov.b64 {%0, %1}, %2;" : "=f"(x), "=f"(y) : "l"(d))

__device__ __forceinline__ float sigf(float x) {
    return __fdividef(1.0f, 1.0f + __expf(-x));
}
__device__ __forceinline__ float tanh_fast(float x) {
    return 1.0f - __fdividef(2.0f, __expf(2.0f * x) + 1.0f);
}
__device__ __forceinline__ float scanp(float p, int n) {
    float v1 = __shfl_up_sync(0xffffffffu, p, 1, 16);
    float v2 = __shfl_up_sync(0xffffffffu, p, 2, 16);
    float v3 = __shfl_up_sync(0xffffffffu, p, 3, 16);
    float m = ((n >= 1) ? v1 : 1.0f) * ((n >= 2) ? v2 : 1.0f);
    p *= m * ((n >= 3) ? v3 : 1.0f);
    float w1 = __shfl_up_sync(0xffffffffu, p, 4, 16);
    float w2 = __shfl_up_sync(0xffffffffu, p, 8, 16);
    float w3 = __shfl_up_sync(0xffffffffu, p, 12, 16);
    float mm = ((n >= 4) ? w1 : 1.0f) * ((n >= 8) ? w2 : 1.0f);
    return p * (mm * ((n >= 12) ? w3 : 1.0f));
}

__global__ __launch_bounds__(128) void qlstm_p2(
    const float* __restrict__ W, float* __restrict__ out, const int write_final)
{
    const int tid = threadIdx.x;
    const int n   = tid & 15;
    const int e   = blockIdx.x * 8 + (tid >> 4);

    // packed weights: Wab[j] = (W_f[n][j], W_i[n][j]), Wcd[j] = (W_g, W_o)
    unsigned long long Wab[16], Wcd[16];
#pragma unroll
    for (int j = 0; j < 16; j++) {
        const float w0 = W[(size_t)(0 * 16 + n) * 144 + 128 + j];
        const float w1 = W[(size_t)(1 * 16 + n) * 144 + 128 + j];
        const float w2 = W[(size_t)(2 * 16 + n) * 144 + 128 + j];
        const float w3 = W[(size_t)(3 * 16 + n) * 144 + 128 + j];
        PACK2(Wab[j], w0, w1);
        PACK2(Wcd[j], w2, w3);
    }

    float c = 0.0f, h = 0.0f;

    const size_t SS = (size_t)B_DIM * GN;
    const float* zp = g_zx + (size_t)e * GN + n;
    float* outp = out + (size_t)e * NQ + n;

    float zc[4][4];
#pragma unroll
    for (int s = 0; s < 4; s++)
#pragma unroll
        for (int g = 0; g < 4; g++) zc[s][g] = zp[s * SS + g * 16];
    zp += 4 * SS;

    for (int tb = 0; tb < 64; ++tb) {
        float zn[4][4];
#pragma unroll
        for (int s = 0; s < 4; s++)
#pragma unroll
            for (int g = 0; g < 4; g++) zn[s][g] = zp[s * SS + g * 16];
        zp += 4 * SS;

#pragma unroll
        for (int s = 0; s < 4; s++) {
            // packed dot accumulators, 2-way split for ILP
            unsigned long long ab0, ab1, cd0, cd1;
            PACK2(ab0, zc[s][0], zc[s][1]);
            PACK2(cd0, zc[s][2], zc[s][3]);
            PACK2(ab1, 0.0f, 0.0f);
            PACK2(cd1, 0.0f, 0.0f);
#pragma unroll
            for (int j = 0; j < 8; j++) {
                const float hj0 = __shfl_sync(0xffffffffu, h, j, 16);
                const float hj1 = __shfl_sync(0xffffffffu, h, j + 8, 16);
                unsigned long long h20, h21;
                PACK2(h20, hj0, hj0);
                PACK2(h21, hj1, hj1);
                FMA_X2(ab0, h20, Wab[j], ab0);
                FMA_X2(cd0, h20, Wcd[j], cd0);
                FMA_X2(ab1, h21, Wab[j + 8], ab1);
                FMA_X2(cd1, h21, Wcd[j + 8], cd1);
            }
            float za, zb, zcv, zd, t0, t1;
            UNPACK2(za, zb, ab0); UNPACK2(t0, t1, ab1);
            za += t0; zb += t1;
            UNPACK2(zcv, zd, cd0); UNPACK2(t0, t1, cd1);
            zcv += t0; zd += t1;

            const float q0 = scanp(__cosf(za), n);
            const float q1 = scanp(__cosf(zb), n);
            const float q2 = scanp(__cosf(zcv), n);
            const float q3 = scanp(__cosf(zd), n);

            const float f  = sigf(q0);
            const float ii = sigf(q1);
            const float gg = tanh_fast(q2);
            const float oo = sigf(q3);
            c = fmaf(f, c, ii * gg);
            h = oo * tanh_fast(c);

            outp[0] = h;
            outp += B_DIM * NQ;
        }
#pragma unroll
        for (int s = 0; s < 4; s++)
#pragma unroll
            for (int g = 0; g < 4; g++) zc[s][g] = zn[s][g];
    }

    if (write_final) {
        float* hx = out + (size_t)T_DIM * B_DIM * NQ;
        hx[(size_t)e * NQ + n] = h;
        hx[(size_t)B_DIM * NQ + (size_t)e * NQ + n] = c;
    }
}

// ---------------------------------------------------------------------------
extern "C" void kernel_launch(void* const* d_in, const int* in_sizes, int n_in,
                              void* d_out, int out_size) {
    const float* X  = (const float*)d_in[0];
    const float* W  = (const float*)d_in[1];
    const float* Bb = (const float*)d_in[2];
    const float* Th = (const float*)d_in[3];
    float* out = (float*)d_out;

    cudaFuncSetAttribute(qlstm_p1, cudaFuncAttributeMaxDynamicSharedMemorySize,
                         P1_SMEM);
    qlstm_p1<<<M_TOT / 128, 256, P1_SMEM>>>(X, W, Bb, Th);

    const int need = T_DIM * B_DIM * NQ + 2 * B_DIM * NQ;
    const int wf = (out_size >= need) ? 1 : 0;
    qlstm_p2<<<B_DIM / 8, 128>>>(W, out, wf);
}

// round 7
// speedup vs baseline: 1.5085x; 1.5085x over previous
#include <cuda_runtime.h>
#include <cstdint>
#include <cstddef>

#define T_DIM 256
#define B_DIM 2048
#define DIN   128
#define NQ    16
#define GN    64
#define M_TOT (T_DIM * B_DIM)

// ZX scratch padded by 4 timesteps so phase-2 prefetch needs no bounds check.
__device__ __align__(256) float g_zx[(size_t)(T_DIM + 4) * B_DIM * GN];

// ===========================================================================
// Phase 1 (R5, measured 136.5us): ZX = X @ Wx^T + (b+theta) via mma.sync
// m16n8k16 bf16, 3xBF16 split (hh + lh + hl; dropped ll ~ 2^-18).
// ===========================================================================
#define SROW8 20                          // uint2 per row
#define WS_OFF 256
#define XS_OFF (WS_OFF + 64 * SROW8 * 8)      // 10496
#define P1_SMEM (XS_OFF + 256 * SROW8 * 8)    // 51456

__device__ __forceinline__ uint2 bf16_split2(float x, float y) {
    uint32_t h, l;
    asm("cvt.rn.bf16x2.f32 %0, %1, %2;" : "=r"(h) : "f"(y), "f"(x));
    const float hx = __uint_as_float(h << 16);
    const float hy = __uint_as_float(h & 0xffff0000u);
    const float lx = x - hx, ly = y - hy;
    asm("cvt.rn.bf16x2.f32 %0, %1, %2;" : "=r"(l) : "f"(ly), "f"(lx));
    return make_uint2(h, l);
}

#define MMA_BF16(c, a0, a1, a2, a3, b0, b1) \
    asm volatile("mma.sync.aligned.m16n8k16.row.col.f32.bf16.bf16.f32 " \
        "{%0,%1,%2,%3}, {%4,%5,%6,%7}, {%8,%9}, {%0,%1,%2,%3};" \
        : "+f"((c)[0]), "+f"((c)[1]), "+f"((c)[2]), "+f"((c)[3]) \
        : "r"(a0), "r"(a1), "r"(a2), "r"(a3), "r"(b0), "r"(b1))

__global__ __launch_bounds__(256, 2) void qlstm_p1(
    const float* __restrict__ X,
    const float* __restrict__ W,      // [64][144]
    const float* __restrict__ Bb,
    const float* __restrict__ Th)
{
    extern __shared__ char smem[];
    float* bts = (float*)smem;
    uint2* Ws2 = (uint2*)(smem + WS_OFF);   // [n=64][kp], stride 20
    uint2* Xs2 = (uint2*)(smem + XS_OFF);   // [row=256][kp], stride 20

    const int tid  = threadIdx.x;
    const int lane = tid & 31, w = tid >> 5;
    const int g = lane >> 2, tig = lane & 3;
    const int rb = w * 32;
    const size_t m0 = (size_t)blockIdx.x * 256;

    if (tid < 64) bts[tid] = Bb[tid] + Th[tid];

    const int sr = tid >> 3, sq = tid & 7;

    float C[2][8][4];
#pragma unroll
    for (int s = 0; s < 2; s++)
#pragma unroll
        for (int nt = 0; nt < 8; nt++)
#pragma unroll
            for (int q = 0; q < 4; q++) C[s][nt][q] = 0.0f;

    float4 xr[8], wr[2];
#pragma unroll
    for (int i = 0; i < 8; i++)
        xr[i] = *(const float4*)(X + (m0 + sr + 32 * i) * DIN + 4 * sq);
#pragma unroll
    for (int i = 0; i < 2; i++)
        wr[i] = *(const float4*)(W + (sr + 32 * i) * 144 + 4 * sq);

    for (int kc = 0; kc < 4; kc++) {
#pragma unroll
        for (int i = 0; i < 8; i++) {
            const uint2 u0 = bf16_split2(xr[i].x, xr[i].y);
            const uint2 u1 = bf16_split2(xr[i].z, xr[i].w);
            *(uint4*)&Xs2[(sr + 32 * i) * SROW8 + 2 * sq] =
                make_uint4(u0.x, u0.y, u1.x, u1.y);
        }
#pragma unroll
        for (int i = 0; i < 2; i++) {
            const uint2 u0 = bf16_split2(wr[i].x, wr[i].y);
            const uint2 u1 = bf16_split2(wr[i].z, wr[i].w);
            *(uint4*)&Ws2[(sr + 32 * i) * SROW8 + 2 * sq] =
                make_uint4(u0.x, u0.y, u1.x, u1.y);
        }
        __syncthreads();

        if (kc < 3) {
            const int kb = (kc + 1) * 32;
#pragma unroll
            for (int i = 0; i < 8; i++)
                xr[i] = *(const float4*)(X + (m0 + sr + 32 * i) * DIN + kb + 4 * sq);
#pragma unroll
            for (int i = 0; i < 2; i++)
                wr[i] = *(const float4*)(W + (sr + 32 * i) * 144 + kb + 4 * sq);
        }

#pragma unroll
        for (int ks = 0; ks < 2; ks++) {
            const int kp = ks * 8 + tig;
            const uint2 A0 = Xs2[(rb + g) * SROW8 + kp];
            const uint2 A1 = Xs2[(rb + 8 + g) * SROW8 + kp];
            const uint2 A2 = Xs2[(rb + g) * SROW8 + kp + 4];
            const uint2 A3 = Xs2[(rb + 8 + g) * SROW8 + kp + 4];
            const uint2 D0 = Xs2[(rb + 16 + g) * SROW8 + kp];
            const uint2 D1 = Xs2[(rb + 24 + g) * SROW8 + kp];
            const uint2 D2 = Xs2[(rb + 16 + g) * SROW8 + kp + 4];
            const uint2 D3 = Xs2[(rb + 24 + g) * SROW8 + kp + 4];
#pragma unroll
            for (int nt = 0; nt < 8; nt++) {
                const uint2 B0 = Ws2[(nt * 8 + g) * SROW8 + kp];
                const uint2 B1 = Ws2[(nt * 8 + g) * SROW8 + kp + 4];
                MMA_BF16(C[0][nt], A0.x, A1.x, A2.x, A3.x, B0.x, B1.x);
                MMA_BF16(C[0][nt], A0.y, A1.y, A2.y, A3.y, B0.x, B1.x);
                MMA_BF16(C[0][nt], A0.x, A1.x, A2.x, A3.x, B0.y, B1.y);
                MMA_BF16(C[1][nt], D0.x, D1.x, D2.x, D3.x, B0.x, B1.x);
                MMA_BF16(C[1][nt], D0.y, D1.y, D2.y, D3.y, B0.x, B1.x);
                MMA_BF16(C[1][nt], D0.x, D1.x, D2.x, D3.x, B0.y, B1.y);
            }
        }
        __syncthreads();
    }

    float2 bt2[8];
#pragma unroll
    for (int nt = 0; nt < 8; nt++)
        bt2[nt] = *(const float2*)&bts[nt * 8 + 2 * tig];

#pragma unroll
    for (int s = 0; s < 2; s++) {
        const size_t r0 = m0 + rb + 16 * s + g;
#pragma unroll
        for (int nt = 0; nt < 8; nt++) {
            const int col = nt * 8 + 2 * tig;
            *(float2*)&g_zx[r0 * GN + col] =
                make_float2(C[s][nt][0] + bt2[nt].x, C[s][nt][1] + bt2[nt].y);
            *(float2*)&g_zx[(r0 + 8) * GN + col] =
                make_float2(C[s][nt][2] + bt2[nt].x, C[s][nt][3] + bt2[nt].y);
        }
    }
}

// ===========================================================================
// Phase 2: 16 lanes/element, 4 elements per 64-thread block (grid 512).
//   h exchange via smem double buffer + __syncwarp (R4, best measured);
//   dots as genuine PTX fma.rn.f32x2 (32 packed FMA vs 64 FFMA);
//   activations: |q|<=1, |c|<=2.08 -> sigmoid = deg-9 odd poly (no MUFU),
//   tanh = Pade[5/4] (1 rcp). Radix-4 shfl scan; 4-step batched prefetch.
// ===========================================================================
#define FMA_X2(d, a, b, c) \
    asm("fma.rn.f32x2 %0, %1, %2, %3;" : "=l"(d) : "l"(a), "l"(b), "l"(c))
#define PACK2(d, x, y) \
    asm("mov.b64 %0, {%1, %2};" : "=l"(d) : "f"(x), "f"(y))
#define UNPACK2(x, y, d) \
    asm("mov.b64 {%0, %1}, %2;" : "=f"(x), "=f"(y) : "l"(d))

// sigmoid(q) for |q| <= 1: 0.5 + q*(A1 + A3 q^2 + A5 q^4 + A7 q^6 + A9 q^8)
#define SA1 0.25f
#define SA3 (-2.0833333e-2f)
#define SA5 (2.0833333e-3f)
#define SA7 (-2.1081349e-4f)
#define SA9 (2.1356922e-5f)
__device__ __forceinline__ float sig_poly(float q) {
    const float u = q * q;
    float p = fmaf(SA9, u, SA7);
    p = fmaf(p, u, SA5);
    p = fmaf(p, u, SA3);
    p = fmaf(p, u, SA1);
    return fmaf(p, q, 0.5f);
}
// tanh(x) for |x| <= ~2.1: Pade[5/4]  x(x^4+105x^2+945)/(15x^4+420x^2+945)
__device__ __forceinline__ float tanh_pade(float x) {
    const float u = x * x;
    const float n = fmaf(u + 105.0f, u, 945.0f);
    const float d = fmaf(fmaf(15.0f, u, 420.0f), u, 945.0f);
    return __fdividef(x * n, d);
}
__device__ __forceinline__ float scanp(float p, int n) {
    float v1 = __shfl_up_sync(0xffffffffu, p, 1, 16);
    float v2 = __shfl_up_sync(0xffffffffu, p, 2, 16);
    float v3 = __shfl_up_sync(0xffffffffu, p, 3, 16);
    float m = ((n >= 1) ? v1 : 1.0f) * ((n >= 2) ? v2 : 1.0f);
    p *= m * ((n >= 3) ? v3 : 1.0f);
    float w1 = __shfl_up_sync(0xffffffffu, p, 4, 16);
    float w2 = __shfl_up_sync(0xffffffffu, p, 8, 16);
    float w3 = __shfl_up_sync(0xffffffffu, p, 12, 16);
    float mm = ((n >= 4) ? w1 : 1.0f) * ((n >= 8) ? w2 : 1.0f);
    return p * (mm * ((n >= 12) ? w3 : 1.0f));
}

__global__ __launch_bounds__(64) void qlstm_p2(
    const float* __restrict__ W, float* __restrict__ out, const int write_final)
{
    __shared__ float hs[2][4][16];

    const int tid = threadIdx.x;
    const int n   = tid & 15;
    const int grp = tid >> 4;
    const int e   = blockIdx.x * 4 + grp;

    // packed recurrent weights: Wab[j] = (W_f, W_i), Wcd[j] = (W_g, W_o)
    unsigned long long Wab[16], Wcd[16];
#pragma unroll
    for (int j = 0; j < 16; j++) {
        const float w0 = W[(size_t)(0 * 16 + n) * 144 + 128 + j];
        const float w1 = W[(size_t)(1 * 16 + n) * 144 + 128 + j];
        const float w2 = W[(size_t)(2 * 16 + n) * 144 + 128 + j];
        const float w3 = W[(size_t)(3 * 16 + n) * 144 + 128 + j];
        PACK2(Wab[j], w0, w1);
        PACK2(Wcd[j], w2, w3);
    }

    float c = 0.0f, h = 0.0f;
    hs[0][grp][n] = 0.0f;
    __syncwarp();

    const size_t SS = (size_t)B_DIM * GN;
    const float* zp = g_zx + (size_t)e * GN + n;
    float* outp = out + (size_t)e * NQ + n;

    float zc[4][4];
#pragma unroll
    for (int s = 0; s < 4; s++)
#pragma unroll
        for (int g = 0; g < 4; g++) zc[s][g] = zp[s * SS + g * 16];
    zp += 4 * SS;

    for (int tb = 0; tb < 64; ++tb) {
        float zn[4][4];
#pragma unroll
        for (int s = 0; s < 4; s++)
#pragma unroll
            for (int g = 0; g < 4; g++) zn[s][g] = zp[s * SS + g * 16];
        zp += 4 * SS;

#pragma unroll
        for (int s = 0; s < 4; s++) {
            const int buf = s & 1;
            float hv[16];
            {
                const float4* hp = (const float4*)hs[buf][grp];
#pragma unroll
                for (int q = 0; q < 4; q++) {
                    const float4 v = hp[q];
                    hv[4 * q + 0] = v.x; hv[4 * q + 1] = v.y;
                    hv[4 * q + 2] = v.z; hv[4 * q + 3] = v.w;
                }
            }
            // packed dots, 2-way ILP split
            unsigned long long ab0, ab1, cd0, cd1;
            PACK2(ab0, zc[s][0], zc[s][1]);
            PACK2(cd0, zc[s][2], zc[s][3]);
            PACK2(ab1, 0.0f, 0.0f);
            PACK2(cd1, 0.0f, 0.0f);
#pragma unroll
            for (int j = 0; j < 8; j++) {
                unsigned long long h20, h21;
                PACK2(h20, hv[j], hv[j]);
                PACK2(h21, hv[j + 8], hv[j + 8]);
                FMA_X2(ab0, h20, Wab[j], ab0);
                FMA_X2(cd0, h20, Wcd[j], cd0);
                FMA_X2(ab1, h21, Wab[j + 8], ab1);
                FMA_X2(cd1, h21, Wcd[j + 8], cd1);
            }
            float za, zb, zg, zo, t0, t1;
            UNPACK2(za, zb, ab0); UNPACK2(t0, t1, ab1);
            za += t0; zb += t1;
            UNPACK2(zg, zo, cd0); UNPACK2(t0, t1, cd1);
            zg += t0; zo += t1;

            const float q0 = scanp(__cosf(za), n);
            const float q1 = scanp(__cosf(zb), n);
            const float q2 = scanp(__cosf(zg), n);
            const float q3 = scanp(__cosf(zo), n);

            const float f  = sig_poly(q0);
            const float ii = sig_poly(q1);
            const float gg = tanh_pade(q2);
            const float oo = sig_poly(q3);
            c = fmaf(f, c, ii * gg);
            h = oo * tanh_pade(c);

            outp[0] = h;
            outp += B_DIM * NQ;
            hs[buf ^ 1][grp][n] = h;
            __syncwarp();
        }
#pragma unroll
        for (int s = 0; s < 4; s++)
#pragma unroll
            for (int g = 0; g < 4; g++) zc[s][g] = zn[s][g];
    }

    if (write_final) {
        float* hx = out + (size_t)T_DIM * B_DIM * NQ;
        hx[(size_t)e * NQ + n] = h;
        hx[(size_t)B_DIM * NQ + (size_t)e * NQ + n] = c;
    }
}

// ---------------------------------------------------------------------------
extern "C" void kernel_launch(void* const* d_in, const int* in_sizes, int n_in,
                              void* d_out, int out_size) {
    const float* X  = (const float*)d_in[0];
    const float* W  = (const float*)d_in[1];
    const float* Bb = (const float*)d_in[2];
    const float* Th = (const float*)d_in[3];
    float* out = (float*)d_out;

    cudaFuncSetAttribute(qlstm_p1, cudaFuncAttributeMaxDynamicSharedMemorySize,
                         P1_SMEM);
    qlstm_p1<<<M_TOT / 256, 256, P1_SMEM>>>(X, W, Bb, Th);

    const int need = T_DIM * B_DIM * NQ + 2 * B_DIM * NQ;
    const int wf = (out_size >= need) ? 1 : 0;
    qlstm_p2<<<B_DIM / 4, 64>>>(W, out, wf);
}